// round 1
// baseline (speedup 1.0000x reference)
#include <cuda_runtime.h>
#include <cstdint>

#define NUM_BITS 16
#define THETA 8
#define HN 4096
#define FF 128
#define CC 10
#define BB 64
#define P0 (FF * NUM_BITS)   // 2048

#define OUT_BLOCKS 24
#define LH_TOTAL (3 * HN)    // 12288
#define LH_PER_BLOCK (LH_TOTAL / OUT_BLOCKS)  // 512

// Scratch (device globals: no allocation allowed in kernel_launch)
__device__ unsigned long long g_act[P0];          // layer-0 input masks
__device__ unsigned long long g_fired[3 * HN];    // per-layer fired masks
__device__ float g_part[OUT_BLOCKS * BB * CC];    // output partial sums

// -------------------------------------------------------------------------
// Encode: x[B,F] -> g_act[p], p = f*16 + t, bit b = (x[b,f] >= (t+1)/17)
// -------------------------------------------------------------------------
__global__ void encode_kernel(const float* __restrict__ x) {
    int p = blockIdx.x * blockDim.x + threadIdx.x;
    if (p >= P0) return;
    int f = p >> 4;
    int t = p & 15;
    float thr = (float)(t + 1) * (1.0f / (float)(NUM_BITS + 1));
    unsigned long long m = 0ull;
#pragma unroll
    for (int b = 0; b < BB; b++) {
        float v = __ldg(&x[b * FF + f]);
        m |= ((unsigned long long)(v >= thr)) << b;
    }
    g_act[p] = m;
}

// -------------------------------------------------------------------------
// Layer: one warp per neuron h. Streams W[h, s, :] (P floats per segment),
// ballots nonzeros, accumulates signed synapse counts per batch (lane L owns
// batches L and L+32), fires if any segment count >= THETA.
// -------------------------------------------------------------------------
template <int P>
__device__ __forceinline__ void process_vec(float4 v, int i, int lane,
                                            const unsigned long long* __restrict__ act,
                                            int& c0, int& c1) {
    float wv[4] = {v.x, v.y, v.z, v.w};
#pragma unroll
    for (int j = 0; j < 4; j++) {
        float w = wv[j];
        unsigned bal = __ballot_sync(0xffffffffu, w != 0.0f);
        while (bal) {
            int src = __ffs(bal) - 1;
            bal &= bal - 1;
            int p = i * 128 + src * 4 + j;
            float ws = __shfl_sync(0xffffffffu, w, src);
            unsigned long long m = __ldg(&act[p]);
            int sgn = (ws > 0.0f) ? 1 : -1;
            c0 += sgn * (int)((m >> lane) & 1ull);
            c1 += sgn * (int)((m >> (lane + 32)) & 1ull);
        }
    }
}

template <int P>
__global__ __launch_bounds__(256) void layer_kernel(
    const float* __restrict__ W,
    const unsigned long long* __restrict__ act,
    unsigned long long* __restrict__ fired) {
    int warp = (blockIdx.x * blockDim.x + threadIdx.x) >> 5;
    int lane = threadIdx.x & 31;
    if (warp >= HN) return;

    unsigned long long fmask = 0ull;
#pragma unroll
    for (int s = 0; s < 2; s++) {
        const float4* row =
            (const float4*)(W + ((size_t)warp * 2 + s) * (size_t)P);
        int c0 = 0, c1 = 0;
        constexpr int NIT = P / 128;   // 16 (P=2048) or 32 (P=4096)
#pragma unroll
        for (int i = 0; i < NIT; i += 4) {
            // 4 independent float4 loads in flight per lane for MLP
            float4 v0 = row[(i + 0) * 32 + lane];
            float4 v1 = row[(i + 1) * 32 + lane];
            float4 v2 = row[(i + 2) * 32 + lane];
            float4 v3 = row[(i + 3) * 32 + lane];
            process_vec<P>(v0, i + 0, lane, act, c0, c1);
            process_vec<P>(v1, i + 1, lane, act, c0, c1);
            process_vec<P>(v2, i + 2, lane, act, c0, c1);
            process_vec<P>(v3, i + 3, lane, act, c0, c1);
        }
        unsigned lo = __ballot_sync(0xffffffffu, c0 >= THETA);
        unsigned hi = __ballot_sync(0xffffffffu, c1 >= THETA);
        fmask |= ((unsigned long long)hi << 32) | (unsigned long long)lo;
    }
    fired[warp] = fmask;
}

// -------------------------------------------------------------------------
// Output stage 1: partial sums over (l,h) slices.
// thread t: c = t/64, b = t%64 -> warp lanes share c, so outW load is a
// warp-uniform broadcast. fired[] load is block-uniform (L1 broadcast).
// -------------------------------------------------------------------------
__global__ __launch_bounds__(640) void out_partial_kernel(
    const float* __restrict__ oW,
    const unsigned long long* __restrict__ fired,
    float* __restrict__ part) {
    int t = threadIdx.x;          // 0..639
    int b = t & 63;
    int c = t >> 6;
    int start = blockIdx.x * LH_PER_BLOCK;
    float acc = 0.0f;
#pragma unroll 8
    for (int i = 0; i < LH_PER_BLOCK; i++) {
        int lh = start + i;       // flat l*H + h
        unsigned long long m = __ldg(&fired[lh]);
        float w = __ldg(&oW[lh * CC + c]);
        acc += w * (float)((m >> b) & 1ull);
    }
    part[blockIdx.x * (BB * CC) + t] = acc;
}

// Output stage 2: deterministic fixed-order reduction of partials.
__global__ void out_reduce_kernel(const float* __restrict__ part,
                                  float* __restrict__ out) {
    int t = threadIdx.x;
    if (t >= BB * CC) return;
    float s = 0.0f;
#pragma unroll
    for (int k = 0; k < OUT_BLOCKS; k++) s += part[k * (BB * CC) + t];
    int b = t & 63;
    int c = t >> 6;
    out[b * CC + c] = s;
}

// -------------------------------------------------------------------------
extern "C" void kernel_launch(void* const* d_in, const int* in_sizes, int n_in,
                              void* d_out, int out_size) {
    const float* x  = (const float*)d_in[0];
    const float* W0 = (const float*)d_in[1];
    const float* W1 = (const float*)d_in[2];
    const float* W2 = (const float*)d_in[3];
    const float* oW = (const float*)d_in[4];
    float* out = (float*)d_out;

    unsigned long long* act = nullptr;
    unsigned long long* fired = nullptr;
    float* part = nullptr;
    cudaGetSymbolAddress((void**)&act, g_act);
    cudaGetSymbolAddress((void**)&fired, g_fired);
    cudaGetSymbolAddress((void**)&part, g_part);

    encode_kernel<<<(P0 + 255) / 256, 256>>>(x);
    // one warp per neuron: 4096 warps = 512 blocks * 8 warps
    layer_kernel<P0><<<512, 256>>>(W0, act, fired);
    layer_kernel<HN><<<512, 256>>>(W1, fired, fired + HN);
    layer_kernel<HN><<<512, 256>>>(W2, fired + HN, fired + 2 * HN);
    out_partial_kernel<<<OUT_BLOCKS, BB * CC>>>(oW, fired, part);
    out_reduce_kernel<<<1, BB * CC>>>(part, out);
}

// round 2
// speedup vs baseline: 1.4099x; 1.4099x over previous
#include <cuda_runtime.h>
#include <cstdint>

#define NUM_BITS 16
#define THETA 8
#define HN 4096
#define FF 128
#define CC 10
#define BB 64
#define P0 (FF * NUM_BITS)   // 2048

#define OUT_BLOCKS 96
#define LH_TOTAL (3 * HN)                      // 12288
#define LH_PER_BLOCK (LH_TOTAL / OUT_BLOCKS)   // 128

// Scratch (device globals: no allocation allowed in kernel_launch)
__device__ unsigned long long g_act[P0];          // layer-0 input masks
__device__ unsigned long long g_fired[3 * HN];    // per-layer fired masks
__device__ float g_part[OUT_BLOCKS * BB * CC];    // output partial sums

// -------------------------------------------------------------------------
// Zero the fired masks (layer kernels OR into them).
// -------------------------------------------------------------------------
__global__ void zero_fired_kernel() {
    int i = blockIdx.x * blockDim.x + threadIdx.x;
    if (i < 3 * HN) g_fired[i] = 0ull;
}

// -------------------------------------------------------------------------
// Encode: x[B,F] -> g_act[p], p = f*16 + t, bit b = (x[b,f] >= (t+1)/17)
// -------------------------------------------------------------------------
__global__ void encode_kernel(const float* __restrict__ x) {
    int p = blockIdx.x * blockDim.x + threadIdx.x;
    if (p >= P0) return;
    int f = p >> 4;
    int t = p & 15;
    float thr = (float)(t + 1) * (1.0f / (float)(NUM_BITS + 1));
    unsigned long long m = 0ull;
#pragma unroll
    for (int b = 0; b < BB; b++) {
        float v = __ldg(&x[b * FF + f]);
        m |= ((unsigned long long)(v >= thr)) << b;
    }
    g_act[p] = m;
}

// -------------------------------------------------------------------------
// Layer: one warp per (neuron, segment). Streams W[h, s, :] with float4
// loads, ballots once per float4 (any-nonzero), shfl-broadcasts hit vectors,
// accumulates signed synapse counts per batch (lane L owns batches L, L+32).
// Fires (count >= THETA) -> atomicOr into fired[h].
// -------------------------------------------------------------------------
template <int P>
__device__ __forceinline__ void process_hits(
    float4 v, int i, int lane,
    const unsigned long long* __restrict__ act,
    int& c0, int& c1) {
    bool nz = (v.x != 0.0f) | (v.y != 0.0f) | (v.z != 0.0f) | (v.w != 0.0f);
    unsigned bal = __ballot_sync(0xffffffffu, nz);
    while (bal) {
        int src = __ffs(bal) - 1;
        bal &= bal - 1;
        float w0 = __shfl_sync(0xffffffffu, v.x, src);
        float w1 = __shfl_sync(0xffffffffu, v.y, src);
        float w2 = __shfl_sync(0xffffffffu, v.z, src);
        float w3 = __shfl_sync(0xffffffffu, v.w, src);
        int pbase = i * 128 + src * 4;
        float wj[4] = {w0, w1, w2, w3};
#pragma unroll
        for (int j = 0; j < 4; j++) {
            float w = wj[j];
            if (w != 0.0f) {
                unsigned long long m = __ldg(&act[pbase + j]);
                unsigned mlo = (unsigned)m;
                unsigned mhi = (unsigned)(m >> 32);
                int sgn = (w > 0.0f) ? 1 : -1;
                c0 += sgn * (int)((mlo >> lane) & 1u);
                c1 += sgn * (int)((mhi >> lane) & 1u);
            }
        }
    }
}

template <int P>
__global__ __launch_bounds__(256) void layer_kernel(
    const float* __restrict__ W,
    const unsigned long long* __restrict__ act,
    unsigned long long* __restrict__ fired) {
    int gw = (blockIdx.x * blockDim.x + threadIdx.x) >> 5;  // 0 .. 2*HN-1
    int lane = threadIdx.x & 31;
    if (gw >= 2 * HN) return;
    int h = gw >> 1;
    int s = gw & 1;

    const float4* row = (const float4*)(W + ((size_t)h * 2 + s) * (size_t)P);
    int c0 = 0, c1 = 0;
    constexpr int NIT = P / 128;   // 16 (P=2048) or 32 (P=4096)
#pragma unroll
    for (int i = 0; i < NIT; i += 8) {
        // 8 independent float4 loads in flight per lane
        float4 v0 = row[(i + 0) * 32 + lane];
        float4 v1 = row[(i + 1) * 32 + lane];
        float4 v2 = row[(i + 2) * 32 + lane];
        float4 v3 = row[(i + 3) * 32 + lane];
        float4 v4 = row[(i + 4) * 32 + lane];
        float4 v5 = row[(i + 5) * 32 + lane];
        float4 v6 = row[(i + 6) * 32 + lane];
        float4 v7 = row[(i + 7) * 32 + lane];
        process_hits<P>(v0, i + 0, lane, act, c0, c1);
        process_hits<P>(v1, i + 1, lane, act, c0, c1);
        process_hits<P>(v2, i + 2, lane, act, c0, c1);
        process_hits<P>(v3, i + 3, lane, act, c0, c1);
        process_hits<P>(v4, i + 4, lane, act, c0, c1);
        process_hits<P>(v5, i + 5, lane, act, c0, c1);
        process_hits<P>(v6, i + 6, lane, act, c0, c1);
        process_hits<P>(v7, i + 7, lane, act, c0, c1);
    }
    unsigned lo = __ballot_sync(0xffffffffu, c0 >= THETA);
    unsigned hi = __ballot_sync(0xffffffffu, c1 >= THETA);
    if (lane == 0) {
        unsigned long long fm =
            ((unsigned long long)hi << 32) | (unsigned long long)lo;
        if (fm) atomicOr(&fired[h], fm);
    }
}

// -------------------------------------------------------------------------
// Output stage 1: partial sums over (l,h) slices.
// thread t: c = t/64, b = t%64 -> outW load is warp-uniform broadcast,
// fired[] load is block-uniform (L1 broadcast).
// -------------------------------------------------------------------------
__global__ __launch_bounds__(640) void out_partial_kernel(
    const float* __restrict__ oW,
    const unsigned long long* __restrict__ fired,
    float* __restrict__ part) {
    int t = threadIdx.x;          // 0..639
    int b = t & 63;
    int c = t >> 6;
    int start = blockIdx.x * LH_PER_BLOCK;
    float acc = 0.0f;
#pragma unroll 8
    for (int i = 0; i < LH_PER_BLOCK; i++) {
        int lh = start + i;       // flat l*H + h
        unsigned long long m = __ldg(&fired[lh]);
        float w = __ldg(&oW[lh * CC + c]);
        acc += w * (float)((m >> b) & 1ull);
    }
    part[blockIdx.x * (BB * CC) + t] = acc;
}

// Output stage 2: deterministic fixed-order reduction of partials.
__global__ void out_reduce_kernel(const float* __restrict__ part,
                                  float* __restrict__ out) {
    int t = threadIdx.x;
    if (t >= BB * CC) return;
    float s = 0.0f;
#pragma unroll
    for (int k = 0; k < OUT_BLOCKS; k++) s += part[k * (BB * CC) + t];
    int b = t & 63;
    int c = t >> 6;
    out[b * CC + c] = s;
}

// -------------------------------------------------------------------------
extern "C" void kernel_launch(void* const* d_in, const int* in_sizes, int n_in,
                              void* d_out, int out_size) {
    const float* x  = (const float*)d_in[0];
    const float* W0 = (const float*)d_in[1];
    const float* W1 = (const float*)d_in[2];
    const float* W2 = (const float*)d_in[3];
    const float* oW = (const float*)d_in[4];
    float* out = (float*)d_out;

    unsigned long long* act = nullptr;
    unsigned long long* fired = nullptr;
    float* part = nullptr;
    cudaGetSymbolAddress((void**)&act, g_act);
    cudaGetSymbolAddress((void**)&fired, g_fired);
    cudaGetSymbolAddress((void**)&part, g_part);

    zero_fired_kernel<<<(3 * HN + 255) / 256, 256>>>();
    encode_kernel<<<(P0 + 255) / 256, 256>>>(x);
    // one warp per (neuron, segment): 8192 warps = 1024 blocks * 8 warps
    layer_kernel<P0><<<1024, 256>>>(W0, act, fired);
    layer_kernel<HN><<<1024, 256>>>(W1, fired, fired + HN);
    layer_kernel<HN><<<1024, 256>>>(W2, fired + HN, fired + 2 * HN);
    out_partial_kernel<<<OUT_BLOCKS, BB * CC>>>(oW, fired, part);
    out_reduce_kernel<<<1, BB * CC>>>(part, out);
}